// round 9
// baseline (speedup 1.0000x reference)
#include <cuda_runtime.h>
#include <math.h>
#include <float.h>
#include <stdint.h>

// Problem constants (fixed by the dataset)
#define LL 4
#define BB 256
#define CC 512
#define SS 64
#define NPTS 50000
#define KSEL 21   // k+1 smallest needed

// -------- scratch (static device globals; no runtime allocation) --------
__device__ float g_q[LL * BB * CC];            // 2 MB
__device__ float g_q2[LL * BB];
__device__ float g_d2[(size_t)LL * BB * NPTS]; // 204.8 MB

// ============================================================
// Kernel 1: q[l,b,c] = mean_s feats[l,b,c,s]   (one warp per row of 64)
// ============================================================
__global__ void qmean_kernel(const float* __restrict__ feats) {
    int gw = (blockIdx.x * blockDim.x + threadIdx.x) >> 5;
    int lane = threadIdx.x & 31;
    if (gw >= LL * BB * CC) return;
    const float* p = feats + (size_t)gw * SS;
    float s = p[lane] + p[lane + 32];
    #pragma unroll
    for (int o = 16; o > 0; o >>= 1) s += __shfl_xor_sync(0xFFFFFFFFu, s, o);
    if (lane == 0) g_q[gw] = s * (1.0f / 64.0f);
}

// ============================================================
// Kernel 2: q2[l,b] = sum_c q^2     (one warp per row of 512)
// ============================================================
__global__ void q2_kernel() {
    int gw = (blockIdx.x * blockDim.x + threadIdx.x) >> 5;
    int lane = threadIdx.x & 31;
    if (gw >= LL * BB) return;
    const float* p = g_q + (size_t)gw * CC;
    float s = 0.f;
    #pragma unroll
    for (int j = 0; j < CC / 32; j++) {
        float v = p[lane + 32 * j];
        s = fmaf(v, v, s);
    }
    #pragma unroll
    for (int o = 16; o > 0; o >>= 1) s += __shfl_xor_sync(0xFFFFFFFFu, s, o);
    if (lane == 0) g_q2[gw] = s;
}

// ============================================================
// mma.sync m16n8k8 tf32 helpers
// ============================================================
__device__ __forceinline__ uint32_t f2tf32(float f) {
    uint32_t r;
    asm("cvt.rna.tf32.f32 %0, %1;" : "=r"(r) : "f"(f));
    return r;
}
__device__ __forceinline__ void mma_tf32(float* c, const uint32_t* a, const uint32_t* b) {
    asm volatile(
        "mma.sync.aligned.m16n8k8.row.col.f32.tf32.tf32.f32 "
        "{%0,%1,%2,%3}, {%4,%5,%6,%7}, {%8,%9}, {%0,%1,%2,%3};"
        : "+f"(c[0]), "+f"(c[1]), "+f"(c[2]), "+f"(c[3])
        : "r"(a[0]), "r"(a[1]), "r"(a[2]), "r"(a[3]), "r"(b[0]), "r"(b[1]));
}

// ============================================================
// Kernel 3: tf32 mma GEMM + fused b2 + d2 epilogue
//   Double-buffered smem (2 stages): per k-iter
//     LDG prefetch -> mma(stage s) -> STS(stage s^1) -> one sync.
// ============================================================
#define Bb 128
#define Bn 128
#define Bk 16
#define LDT 20           // smem row stride in words (16 + 4 pad, conflict-free)
#define TSZ (Bb * LDT)   // words per stage per matrix (2560)

__global__ __launch_bounds__(256, 2)
void gemm_mma_kernel(const float* __restrict__ bank) {
    __shared__ uint32_t As[2 * TSZ];   // q tile,    [stage][m][k]
    __shared__ uint32_t Bs[2 * TSZ];   // bank tile, [stage][n][k]
    __shared__ float q2s[Bb];
    __shared__ float b2s[Bn];

    const int l  = blockIdx.z;
    const int m0 = blockIdx.x * Bb;
    const int n0 = blockIdx.y * Bn;
    const int nrem = NPTS - n0;

    const float* Ap = g_q  + ((size_t)l * BB   + m0) * CC;
    const float* Bp = bank + ((size_t)l * NPTS + n0) * CC;

    const int tid  = threadIdx.x;
    const int lane = tid & 31;
    const int wid  = tid >> 5;
    const int wm   = wid & 1;
    const int wn   = wid >> 1;
    const int gr   = lane >> 2;
    const int tg   = lane & 3;

    const int lrow = tid >> 2;
    const int lk4  = (tid & 3) * 4;
    const bool bok0 = (lrow      < nrem);
    const bool bok1 = (lrow + 64 < nrem);

    const float* ap0 = Ap + (size_t)lrow * CC + lk4;
    const float* ap1 = Ap + (size_t)(lrow + 64) * CC + lk4;
    const float* bp0 = Bp + (size_t)lrow * CC + lk4;
    const float* bp1 = Bp + (size_t)(lrow + 64) * CC + lk4;

    float c[4][4][4];
    #pragma unroll
    for (int i = 0; i < 4; i++)
        #pragma unroll
        for (int j = 0; j < 4; j++)
            #pragma unroll
            for (int t = 0; t < 4; t++) c[i][j][t] = 0.f;

    float ssq0 = 0.f, ssq1 = 0.f;
    const float4 z4 = make_float4(0.f, 0.f, 0.f, 0.f);

    // ---- prologue: tile 0 -> regs -> stage 0 ----
    float4 pa0 = *(const float4*)(ap0);
    float4 pa1 = *(const float4*)(ap1);
    float4 pb0 = bok0 ? *(const float4*)(bp0) : z4;
    float4 pb1 = bok1 ? *(const float4*)(bp1) : z4;
    {
        *(uint4*)&As[lrow * LDT + lk4] =
            make_uint4(f2tf32(pa0.x), f2tf32(pa0.y), f2tf32(pa0.z), f2tf32(pa0.w));
        *(uint4*)&As[(lrow + 64) * LDT + lk4] =
            make_uint4(f2tf32(pa1.x), f2tf32(pa1.y), f2tf32(pa1.z), f2tf32(pa1.w));
        ssq0 = fmaf(pb0.x, pb0.x, ssq0); ssq0 = fmaf(pb0.y, pb0.y, ssq0);
        ssq0 = fmaf(pb0.z, pb0.z, ssq0); ssq0 = fmaf(pb0.w, pb0.w, ssq0);
        *(uint4*)&Bs[lrow * LDT + lk4] =
            make_uint4(f2tf32(pb0.x), f2tf32(pb0.y), f2tf32(pb0.z), f2tf32(pb0.w));
        ssq1 = fmaf(pb1.x, pb1.x, ssq1); ssq1 = fmaf(pb1.y, pb1.y, ssq1);
        ssq1 = fmaf(pb1.z, pb1.z, ssq1); ssq1 = fmaf(pb1.w, pb1.w, ssq1);
        *(uint4*)&Bs[(lrow + 64) * LDT + lk4] =
            make_uint4(f2tf32(pb1.x), f2tf32(pb1.y), f2tf32(pb1.z), f2tf32(pb1.w));
    }
    __syncthreads();

    int s = 0;
    #pragma unroll 1
    for (int k0 = 0; k0 < CC; k0 += Bk) {
        const int kn = k0 + Bk;
        const bool have_next = (kn < CC);
        // ---- prefetch next tile into registers ----
        if (have_next) {
            pa0 = *(const float4*)(ap0 + kn);
            pa1 = *(const float4*)(ap1 + kn);
            pb0 = bok0 ? *(const float4*)(bp0 + kn) : z4;
            pb1 = bok1 ? *(const float4*)(bp1 + kn) : z4;
        }

        // ---- mma on stage s ----
        const uint32_t so = (uint32_t)s * TSZ;
        #pragma unroll
        for (int ks = 0; ks < Bk; ks += 8) {
            uint32_t a[4][4], b[4][2];
            #pragma unroll
            for (int mt = 0; mt < 4; mt++) {
                int base = so + (wm * 64 + mt * 16 + gr) * LDT + ks + tg;
                a[mt][0] = As[base];
                a[mt][1] = As[base + 8 * LDT];
                a[mt][2] = As[base + 4];
                a[mt][3] = As[base + 8 * LDT + 4];
            }
            #pragma unroll
            for (int nt = 0; nt < 4; nt++) {
                int base = so + (wn * 32 + nt * 8 + gr) * LDT + ks + tg;
                b[nt][0] = Bs[base];
                b[nt][1] = Bs[base + 4];
            }
            #pragma unroll
            for (int mt = 0; mt < 4; mt++)
                #pragma unroll
                for (int nt = 0; nt < 4; nt++)
                    mma_tf32(c[mt][nt], a[mt], b[nt]);
        }

        // ---- commit prefetched tile to the other stage, single sync ----
        if (have_next) {
            const uint32_t to = (uint32_t)(s ^ 1) * TSZ;
            *(uint4*)&As[to + lrow * LDT + lk4] =
                make_uint4(f2tf32(pa0.x), f2tf32(pa0.y), f2tf32(pa0.z), f2tf32(pa0.w));
            *(uint4*)&As[to + (lrow + 64) * LDT + lk4] =
                make_uint4(f2tf32(pa1.x), f2tf32(pa1.y), f2tf32(pa1.z), f2tf32(pa1.w));
            ssq0 = fmaf(pb0.x, pb0.x, ssq0); ssq0 = fmaf(pb0.y, pb0.y, ssq0);
            ssq0 = fmaf(pb0.z, pb0.z, ssq0); ssq0 = fmaf(pb0.w, pb0.w, ssq0);
            *(uint4*)&Bs[to + lrow * LDT + lk4] =
                make_uint4(f2tf32(pb0.x), f2tf32(pb0.y), f2tf32(pb0.z), f2tf32(pb0.w));
            ssq1 = fmaf(pb1.x, pb1.x, ssq1); ssq1 = fmaf(pb1.y, pb1.y, ssq1);
            ssq1 = fmaf(pb1.z, pb1.z, ssq1); ssq1 = fmaf(pb1.w, pb1.w, ssq1);
            *(uint4*)&Bs[to + (lrow + 64) * LDT + lk4] =
                make_uint4(f2tf32(pb1.x), f2tf32(pb1.y), f2tf32(pb1.z), f2tf32(pb1.w));
            s ^= 1;
            __syncthreads();
        }
    }

    // ---- b2 reduce ----
    ssq0 += __shfl_xor_sync(0xFFFFFFFFu, ssq0, 1);
    ssq0 += __shfl_xor_sync(0xFFFFFFFFu, ssq0, 2);
    ssq1 += __shfl_xor_sync(0xFFFFFFFFu, ssq1, 1);
    ssq1 += __shfl_xor_sync(0xFFFFFFFFu, ssq1, 2);
    if ((tid & 3) == 0) {
        b2s[lrow]      = ssq0;
        b2s[lrow + 64] = ssq1;
    }
    if (tid < Bb) q2s[tid] = g_q2[l * BB + m0 + tid];
    __syncthreads();

    // ---- epilogue ----
    #pragma unroll
    for (int mt = 0; mt < 4; mt++) {
        int ml = wm * 64 + mt * 16 + gr;
        float q2a = q2s[ml];
        float q2b = q2s[ml + 8];
        #pragma unroll
        for (int nt = 0; nt < 4; nt++) {
            int nl = wn * 32 + nt * 8 + 2 * tg;
            if (nl < nrem) {
                float b2x = b2s[nl];
                float b2y = b2s[nl + 1];
                float2 r0, r1;
                r0.x = fmaxf(fmaf(-2.f, c[mt][nt][0], q2a + b2x), 0.f);
                r0.y = fmaxf(fmaf(-2.f, c[mt][nt][1], q2a + b2y), 0.f);
                r1.x = fmaxf(fmaf(-2.f, c[mt][nt][2], q2b + b2x), 0.f);
                r1.y = fmaxf(fmaf(-2.f, c[mt][nt][3], q2b + b2y), 0.f);
                size_t base = ((size_t)l * BB + m0 + ml) * NPTS + n0 + nl;
                *(float2*)&g_d2[base]               = r0;
                *(float2*)&g_d2[base + 8 * NPTS]    = r1;
            }
        }
    }
}

// ============================================================
// Kernel 4: per-(l,b) top-21 via threshold-gated candidate buffer
//   CAP 10240 (41 KB), chunks of 8192 elems, 8 LDG.128 in flight.
// ============================================================
#define CAP 10240          // candidate buffer capacity (40 KB)
#define NF4 (NPTS / 4)     // 12500 float4 per row
#define SEEDF4 128         // first 512 elements seed the threshold
#define CHUNKF4 2048       // 8192 elements per chunk = 8 float4/thread

__global__ __launch_bounds__(256)
void topk_lid_kernel(float* __restrict__ out) {
    const int row = blockIdx.x;          // l*BB + b
    const float4* D4 = (const float4*)(g_d2 + (size_t)row * NPTS);
    const int tid = threadIdx.x;
    const int lane = tid & 31;
    const int wid = tid >> 5;

    __shared__ float buf[CAP + 32];
    __shared__ float sel[KSEL];
    __shared__ float wmin[8];
    __shared__ int   wloc[8];
    __shared__ int   cnt;
    __shared__ float tau;

    if (tid < KSEL) sel[tid] = FLT_MAX;
    if (tid == 0) cnt = 0;
    __syncthreads();

    auto merge = [&]() {
        int c = cnt;
        if (tid < KSEL) buf[c + tid] = sel[tid];
        __syncthreads();
        int total = c + KSEL;
        for (int it = 0; it < KSEL; it++) {
            float mv = FLT_MAX; int mi = 0;
            for (int i = tid; i < total; i += 256) {
                float v = buf[i];
                if (v < mv) { mv = v; mi = i; }
            }
            #pragma unroll
            for (int o = 16; o > 0; o >>= 1) {
                float ov = __shfl_xor_sync(0xFFFFFFFFu, mv, o);
                int   oi = __shfl_xor_sync(0xFFFFFFFFu, mi, o);
                if (ov < mv) { mv = ov; mi = oi; }
            }
            if (lane == 0) { wmin[wid] = mv; wloc[wid] = mi; }
            __syncthreads();
            if (tid == 0) {
                float gv = wmin[0]; int gi = wloc[0];
                #pragma unroll
                for (int w = 1; w < 8; w++)
                    if (wmin[w] < gv) { gv = wmin[w]; gi = wloc[w]; }
                sel[it] = gv;
                buf[gi] = FLT_MAX;
            }
            __syncthreads();
        }
        if (tid == 0) { tau = sel[KSEL - 1]; cnt = 0; }
        __syncthreads();
    };

    // ---- seed: first 512 elements ----
    if (tid < SEEDF4) {
        float4 v = D4[tid];
        buf[tid * 4 + 0] = v.x;
        buf[tid * 4 + 1] = v.y;
        buf[tid * 4 + 2] = v.z;
        buf[tid * 4 + 3] = v.w;
    }
    if (tid == 0) cnt = SEEDF4 * 4;
    __syncthreads();
    merge();
    float tauR = tau;

    // ---- scan rest: chunks of 2048 float4, 8 LDG.128 in flight/thread ----
    int base = SEEDF4;
    bool first_chunk = true;
    while (base < NF4) {
        int end = base + CHUNKF4;
        if (end > NF4) end = NF4;
        int i = base + tid;
        // 8 loads in flight
        for (; i + 1792 < end; i += 2048) {
            float4 v0 = D4[i];
            float4 v1 = D4[i + 256];
            float4 v2 = D4[i + 512];
            float4 v3 = D4[i + 768];
            float4 v4 = D4[i + 1024];
            float4 v5 = D4[i + 1280];
            float4 v6 = D4[i + 1536];
            float4 v7 = D4[i + 1792];
            if (v0.x < tauR) { int p = atomicAdd(&cnt, 1); buf[p] = v0.x; }
            if (v0.y < tauR) { int p = atomicAdd(&cnt, 1); buf[p] = v0.y; }
            if (v0.z < tauR) { int p = atomicAdd(&cnt, 1); buf[p] = v0.z; }
            if (v0.w < tauR) { int p = atomicAdd(&cnt, 1); buf[p] = v0.w; }
            if (v1.x < tauR) { int p = atomicAdd(&cnt, 1); buf[p] = v1.x; }
            if (v1.y < tauR) { int p = atomicAdd(&cnt, 1); buf[p] = v1.y; }
            if (v1.z < tauR) { int p = atomicAdd(&cnt, 1); buf[p] = v1.z; }
            if (v1.w < tauR) { int p = atomicAdd(&cnt, 1); buf[p] = v1.w; }
            if (v2.x < tauR) { int p = atomicAdd(&cnt, 1); buf[p] = v2.x; }
            if (v2.y < tauR) { int p = atomicAdd(&cnt, 1); buf[p] = v2.y; }
            if (v2.z < tauR) { int p = atomicAdd(&cnt, 1); buf[p] = v2.z; }
            if (v2.w < tauR) { int p = atomicAdd(&cnt, 1); buf[p] = v2.w; }
            if (v3.x < tauR) { int p = atomicAdd(&cnt, 1); buf[p] = v3.x; }
            if (v3.y < tauR) { int p = atomicAdd(&cnt, 1); buf[p] = v3.y; }
            if (v3.z < tauR) { int p = atomicAdd(&cnt, 1); buf[p] = v3.z; }
            if (v3.w < tauR) { int p = atomicAdd(&cnt, 1); buf[p] = v3.w; }
            if (v4.x < tauR) { int p = atomicAdd(&cnt, 1); buf[p] = v4.x; }
            if (v4.y < tauR) { int p = atomicAdd(&cnt, 1); buf[p] = v4.y; }
            if (v4.z < tauR) { int p = atomicAdd(&cnt, 1); buf[p] = v4.z; }
            if (v4.w < tauR) { int p = atomicAdd(&cnt, 1); buf[p] = v4.w; }
            if (v5.x < tauR) { int p = atomicAdd(&cnt, 1); buf[p] = v5.x; }
            if (v5.y < tauR) { int p = atomicAdd(&cnt, 1); buf[p] = v5.y; }
            if (v5.z < tauR) { int p = atomicAdd(&cnt, 1); buf[p] = v5.z; }
            if (v5.w < tauR) { int p = atomicAdd(&cnt, 1); buf[p] = v5.w; }
            if (v6.x < tauR) { int p = atomicAdd(&cnt, 1); buf[p] = v6.x; }
            if (v6.y < tauR) { int p = atomicAdd(&cnt, 1); buf[p] = v6.y; }
            if (v6.z < tauR) { int p = atomicAdd(&cnt, 1); buf[p] = v6.z; }
            if (v6.w < tauR) { int p = atomicAdd(&cnt, 1); buf[p] = v6.w; }
            if (v7.x < tauR) { int p = atomicAdd(&cnt, 1); buf[p] = v7.x; }
            if (v7.y < tauR) { int p = atomicAdd(&cnt, 1); buf[p] = v7.y; }
            if (v7.z < tauR) { int p = atomicAdd(&cnt, 1); buf[p] = v7.z; }
            if (v7.w < tauR) { int p = atomicAdd(&cnt, 1); buf[p] = v7.w; }
        }
        // remainder
        for (; i < end; i += 256) {
            float4 v = D4[i];
            if (v.x < tauR) { int p = atomicAdd(&cnt, 1); buf[p] = v.x; }
            if (v.y < tauR) { int p = atomicAdd(&cnt, 1); buf[p] = v.y; }
            if (v.z < tauR) { int p = atomicAdd(&cnt, 1); buf[p] = v.z; }
            if (v.w < tauR) { int p = atomicAdd(&cnt, 1); buf[p] = v.w; }
        }
        __syncthreads();
        // tighten tau after first chunk; otherwise only on overflow risk
        if ((first_chunk && cnt > 0) || cnt >= CAP - 8192) {
            merge();
        }
        tauR = tau;
        first_chunk = false;
        base = end;
    }
    if (cnt > 0) merge();

    // ---- LID ----
    if (tid == 0) {
        float rk2 = sel[KSEL - 1];
        float s = 0.f;
        #pragma unroll
        for (int i = 1; i < KSEL - 1; i++)
            s += 0.5f * logf(sel[i] / rk2);
        int l = row / BB;
        int b = row % BB;
        out[b * LL + l] = -(20.0f / s);
    }
}

// ============================================================
extern "C" void kernel_launch(void* const* d_in, const int* in_sizes, int n_in,
                              void* d_out, int out_size) {
    const float* feats = (const float*)d_in[0];
    const float* bank  = (const float*)d_in[1];
    // d_in[2] (k) is fixed at 20 for this problem.

    qmean_kernel<<<(LL * BB * CC) / 8, 256>>>(feats);
    q2_kernel<<<(LL * BB + 7) / 8, 256>>>();

    dim3 gg(2, (NPTS + Bn - 1) / Bn, LL);   // (2, 391, 4)
    gemm_mma_kernel<<<gg, 256>>>(bank);

    topk_lid_kernel<<<LL * BB, 256>>>((float*)d_out);
}

// round 10
// speedup vs baseline: 1.3285x; 1.3285x over previous
#include <cuda_runtime.h>
#include <cuda_fp16.h>
#include <math.h>
#include <float.h>
#include <stdint.h>

// Problem constants (fixed by the dataset)
#define LL 4
#define BB 256
#define CC 512
#define SS 64
#define NPTS 50000
#define KSEL 21   // k+1 smallest needed

// -------- scratch (static device globals; no runtime allocation) --------
__device__ float g_q[LL * BB * CC];            // 2 MB
__device__ float g_q2[LL * BB];
__device__ float g_d2[(size_t)LL * BB * NPTS]; // 204.8 MB

// ============================================================
// Kernel 1: q[l,b,c] = mean_s feats[l,b,c,s]   (one warp per row of 64)
// ============================================================
__global__ void qmean_kernel(const float* __restrict__ feats) {
    int gw = (blockIdx.x * blockDim.x + threadIdx.x) >> 5;
    int lane = threadIdx.x & 31;
    if (gw >= LL * BB * CC) return;
    const float* p = feats + (size_t)gw * SS;
    float s = p[lane] + p[lane + 32];
    #pragma unroll
    for (int o = 16; o > 0; o >>= 1) s += __shfl_xor_sync(0xFFFFFFFFu, s, o);
    if (lane == 0) g_q[gw] = s * (1.0f / 64.0f);
}

// ============================================================
// Kernel 2: q2[l,b] = sum_c q^2     (one warp per row of 512)
// ============================================================
__global__ void q2_kernel() {
    int gw = (blockIdx.x * blockDim.x + threadIdx.x) >> 5;
    int lane = threadIdx.x & 31;
    if (gw >= LL * BB) return;
    const float* p = g_q + (size_t)gw * CC;
    float s = 0.f;
    #pragma unroll
    for (int j = 0; j < CC / 32; j++) {
        float v = p[lane + 32 * j];
        s = fmaf(v, v, s);
    }
    #pragma unroll
    for (int o = 16; o > 0; o >>= 1) s += __shfl_xor_sync(0xFFFFFFFFu, s, o);
    if (lane == 0) g_q2[gw] = s;
}

// ============================================================
// mma.sync m16n8k16 f16 helpers (fp32 accumulate)
// ============================================================
__device__ __forceinline__ uint32_t h2pack(float a, float b) {
    __half2 h = __floats2half2_rn(a, b);
    return *(uint32_t*)&h;
}
__device__ __forceinline__ void mma_f16(float* c, const uint32_t* a, const uint32_t* b) {
    asm volatile(
        "mma.sync.aligned.m16n8k16.row.col.f32.f16.f16.f32 "
        "{%0,%1,%2,%3}, {%4,%5,%6,%7}, {%8,%9}, {%0,%1,%2,%3};"
        : "+f"(c[0]), "+f"(c[1]), "+f"(c[2]), "+f"(c[3])
        : "r"(a[0]), "r"(a[1]), "r"(a[2]), "r"(a[3]), "r"(b[0]), "r"(b[1]));
}

// ============================================================
// Kernel 3: f16 mma GEMM + fused b2 + d2 epilogue
//   Double-buffered smem, BK=16 (one m16n8k16 k-step per iter).
//   Tiles stored as half2 words: [row][k/2], stride 12 words
//   (8 data + 4 pad -> fragment reads hit all 32 banks).
// ============================================================
#define Bb 128
#define Bn 128
#define Bk 16
#define LDT2 12            // words per row (8 half2 + 4 pad)
#define TSZ2 (Bb * LDT2)   // words per stage per matrix (1536)

__global__ __launch_bounds__(256, 2)
void gemm_mma_kernel(const float* __restrict__ bank) {
    __shared__ uint32_t As[2 * TSZ2];   // q tile,    [stage][m][k/2]
    __shared__ uint32_t Bs[2 * TSZ2];   // bank tile, [stage][n][k/2]
    __shared__ float q2s[Bb];
    __shared__ float b2s[Bn];

    const int l  = blockIdx.z;
    const int m0 = blockIdx.x * Bb;
    const int n0 = blockIdx.y * Bn;
    const int nrem = NPTS - n0;

    const float* Ap = g_q  + ((size_t)l * BB   + m0) * CC;
    const float* Bp = bank + ((size_t)l * NPTS + n0) * CC;

    const int tid  = threadIdx.x;
    const int lane = tid & 31;
    const int wid  = tid >> 5;
    const int wm   = wid & 1;
    const int wn   = wid >> 1;
    const int gr   = lane >> 2;
    const int tg   = lane & 3;

    const int lrow = tid >> 2;
    const int lk4  = (tid & 3) * 4;      // k offset of this thread's float4
    const int lw   = lk4 >> 1;           // word offset (half2) in tile row
    const bool bok0 = (lrow      < nrem);
    const bool bok1 = (lrow + 64 < nrem);

    const float* ap0 = Ap + (size_t)lrow * CC + lk4;
    const float* ap1 = Ap + (size_t)(lrow + 64) * CC + lk4;
    const float* bp0 = Bp + (size_t)lrow * CC + lk4;
    const float* bp1 = Bp + (size_t)(lrow + 64) * CC + lk4;

    float c[4][4][4];
    #pragma unroll
    for (int i = 0; i < 4; i++)
        #pragma unroll
        for (int j = 0; j < 4; j++)
            #pragma unroll
            for (int t = 0; t < 4; t++) c[i][j][t] = 0.f;

    float ssq0 = 0.f, ssq1 = 0.f;
    const float4 z4 = make_float4(0.f, 0.f, 0.f, 0.f);

    // ---- prologue: tile 0 -> regs -> stage 0 ----
    float4 pa0 = *(const float4*)(ap0);
    float4 pa1 = *(const float4*)(ap1);
    float4 pb0 = bok0 ? *(const float4*)(bp0) : z4;
    float4 pb1 = bok1 ? *(const float4*)(bp1) : z4;
    {
        *(uint2*)&As[lrow * LDT2 + lw] =
            make_uint2(h2pack(pa0.x, pa0.y), h2pack(pa0.z, pa0.w));
        *(uint2*)&As[(lrow + 64) * LDT2 + lw] =
            make_uint2(h2pack(pa1.x, pa1.y), h2pack(pa1.z, pa1.w));
        ssq0 = fmaf(pb0.x, pb0.x, ssq0); ssq0 = fmaf(pb0.y, pb0.y, ssq0);
        ssq0 = fmaf(pb0.z, pb0.z, ssq0); ssq0 = fmaf(pb0.w, pb0.w, ssq0);
        *(uint2*)&Bs[lrow * LDT2 + lw] =
            make_uint2(h2pack(pb0.x, pb0.y), h2pack(pb0.z, pb0.w));
        ssq1 = fmaf(pb1.x, pb1.x, ssq1); ssq1 = fmaf(pb1.y, pb1.y, ssq1);
        ssq1 = fmaf(pb1.z, pb1.z, ssq1); ssq1 = fmaf(pb1.w, pb1.w, ssq1);
        *(uint2*)&Bs[(lrow + 64) * LDT2 + lw] =
            make_uint2(h2pack(pb1.x, pb1.y), h2pack(pb1.z, pb1.w));
    }
    __syncthreads();

    int s = 0;
    #pragma unroll 1
    for (int k0 = 0; k0 < CC; k0 += Bk) {
        const int kn = k0 + Bk;
        const bool have_next = (kn < CC);
        // ---- prefetch next tile into registers ----
        if (have_next) {
            pa0 = *(const float4*)(ap0 + kn);
            pa1 = *(const float4*)(ap1 + kn);
            pb0 = bok0 ? *(const float4*)(bp0 + kn) : z4;
            pb1 = bok1 ? *(const float4*)(bp1 + kn) : z4;
        }

        // ---- mma on stage s: one m16n8k16 k-step ----
        const uint32_t so = (uint32_t)s * TSZ2;
        {
            uint32_t a[4][4], b[4][2];
            #pragma unroll
            for (int mt = 0; mt < 4; mt++) {
                int base = so + (wm * 64 + mt * 16 + gr) * LDT2 + tg;
                a[mt][0] = As[base];                 // (gr,   k=2tg..2tg+1)
                a[mt][1] = As[base + 8 * LDT2];      // (gr+8, same k)
                a[mt][2] = As[base + 4];             // (gr,   k+8)
                a[mt][3] = As[base + 8 * LDT2 + 4];  // (gr+8, k+8)
            }
            #pragma unroll
            for (int nt = 0; nt < 4; nt++) {
                int base = so + (wn * 32 + nt * 8 + gr) * LDT2 + tg;
                b[nt][0] = Bs[base];                 // (n=gr, k=2tg..2tg+1)
                b[nt][1] = Bs[base + 4];             // (n=gr, k+8)
            }
            #pragma unroll
            for (int mt = 0; mt < 4; mt++)
                #pragma unroll
                for (int nt = 0; nt < 4; nt++)
                    mma_f16(c[mt][nt], a[mt], b[nt]);
        }

        // ---- commit prefetched tile to the other stage, single sync ----
        if (have_next) {
            const uint32_t to = (uint32_t)(s ^ 1) * TSZ2;
            *(uint2*)&As[to + lrow * LDT2 + lw] =
                make_uint2(h2pack(pa0.x, pa0.y), h2pack(pa0.z, pa0.w));
            *(uint2*)&As[to + (lrow + 64) * LDT2 + lw] =
                make_uint2(h2pack(pa1.x, pa1.y), h2pack(pa1.z, pa1.w));
            ssq0 = fmaf(pb0.x, pb0.x, ssq0); ssq0 = fmaf(pb0.y, pb0.y, ssq0);
            ssq0 = fmaf(pb0.z, pb0.z, ssq0); ssq0 = fmaf(pb0.w, pb0.w, ssq0);
            *(uint2*)&Bs[to + lrow * LDT2 + lw] =
                make_uint2(h2pack(pb0.x, pb0.y), h2pack(pb0.z, pb0.w));
            ssq1 = fmaf(pb1.x, pb1.x, ssq1); ssq1 = fmaf(pb1.y, pb1.y, ssq1);
            ssq1 = fmaf(pb1.z, pb1.z, ssq1); ssq1 = fmaf(pb1.w, pb1.w, ssq1);
            *(uint2*)&Bs[to + (lrow + 64) * LDT2 + lw] =
                make_uint2(h2pack(pb1.x, pb1.y), h2pack(pb1.z, pb1.w));
            s ^= 1;
            __syncthreads();
        }
    }

    // ---- b2 reduce ----
    ssq0 += __shfl_xor_sync(0xFFFFFFFFu, ssq0, 1);
    ssq0 += __shfl_xor_sync(0xFFFFFFFFu, ssq0, 2);
    ssq1 += __shfl_xor_sync(0xFFFFFFFFu, ssq1, 1);
    ssq1 += __shfl_xor_sync(0xFFFFFFFFu, ssq1, 2);
    if ((tid & 3) == 0) {
        b2s[lrow]      = ssq0;
        b2s[lrow + 64] = ssq1;
    }
    if (tid < Bb) q2s[tid] = g_q2[l * BB + m0 + tid];
    __syncthreads();

    // ---- epilogue (c frag layout identical to m16n8k8 path) ----
    #pragma unroll
    for (int mt = 0; mt < 4; mt++) {
        int ml = wm * 64 + mt * 16 + gr;
        float q2a = q2s[ml];
        float q2b = q2s[ml + 8];
        #pragma unroll
        for (int nt = 0; nt < 4; nt++) {
            int nl = wn * 32 + nt * 8 + 2 * tg;
            if (nl < nrem) {
                float b2x = b2s[nl];
                float b2y = b2s[nl + 1];
                float2 r0, r1;
                r0.x = fmaxf(fmaf(-2.f, c[mt][nt][0], q2a + b2x), 0.f);
                r0.y = fmaxf(fmaf(-2.f, c[mt][nt][1], q2a + b2y), 0.f);
                r1.x = fmaxf(fmaf(-2.f, c[mt][nt][2], q2b + b2x), 0.f);
                r1.y = fmaxf(fmaf(-2.f, c[mt][nt][3], q2b + b2y), 0.f);
                size_t base = ((size_t)l * BB + m0 + ml) * NPTS + n0 + nl;
                *(float2*)&g_d2[base]               = r0;
                *(float2*)&g_d2[base + 8 * NPTS]    = r1;
            }
        }
    }
}

// ============================================================
// Kernel 4: per-(l,b) top-21 via threshold-gated candidate buffer
//   (exact Round-8 configuration: 25 KB smem, MLP=4, occ ~70%)
// ============================================================
#define CAP 6144           // candidate buffer capacity (24 KB)
#define NF4 (NPTS / 4)     // 12500 float4 per row
#define SEEDF4 128         // first 512 elements seed the threshold
#define CHUNKF4 1024       // 4096 elements per chunk = 4 float4/thread

__global__ __launch_bounds__(256)
void topk_lid_kernel(float* __restrict__ out) {
    const int row = blockIdx.x;          // l*BB + b
    const float4* D4 = (const float4*)(g_d2 + (size_t)row * NPTS);
    const int tid = threadIdx.x;
    const int lane = tid & 31;
    const int wid = tid >> 5;

    __shared__ float buf[CAP + 32];
    __shared__ float sel[KSEL];
    __shared__ float wmin[8];
    __shared__ int   wloc[8];
    __shared__ int   cnt;
    __shared__ float tau;

    if (tid < KSEL) sel[tid] = FLT_MAX;
    if (tid == 0) cnt = 0;
    __syncthreads();

    auto merge = [&]() {
        int c = cnt;
        if (tid < KSEL) buf[c + tid] = sel[tid];
        __syncthreads();
        int total = c + KSEL;
        for (int it = 0; it < KSEL; it++) {
            float mv = FLT_MAX; int mi = 0;
            for (int i = tid; i < total; i += 256) {
                float v = buf[i];
                if (v < mv) { mv = v; mi = i; }
            }
            #pragma unroll
            for (int o = 16; o > 0; o >>= 1) {
                float ov = __shfl_xor_sync(0xFFFFFFFFu, mv, o);
                int   oi = __shfl_xor_sync(0xFFFFFFFFu, mi, o);
                if (ov < mv) { mv = ov; mi = oi; }
            }
            if (lane == 0) { wmin[wid] = mv; wloc[wid] = mi; }
            __syncthreads();
            if (tid == 0) {
                float gv = wmin[0]; int gi = wloc[0];
                #pragma unroll
                for (int w = 1; w < 8; w++)
                    if (wmin[w] < gv) { gv = wmin[w]; gi = wloc[w]; }
                sel[it] = gv;
                buf[gi] = FLT_MAX;
            }
            __syncthreads();
        }
        if (tid == 0) { tau = sel[KSEL - 1]; cnt = 0; }
        __syncthreads();
    };

    // ---- seed: first 512 elements ----
    if (tid < SEEDF4) {
        float4 v = D4[tid];
        buf[tid * 4 + 0] = v.x;
        buf[tid * 4 + 1] = v.y;
        buf[tid * 4 + 2] = v.z;
        buf[tid * 4 + 3] = v.w;
    }
    if (tid == 0) cnt = SEEDF4 * 4;
    __syncthreads();
    merge();
    float tauR = tau;

    // ---- scan rest: chunks of 1024 float4, 4 LDG.128 in flight/thread ----
    int base = SEEDF4;
    bool first_chunk = true;
    while (base < NF4) {
        int end = base + CHUNKF4;
        if (end > NF4) end = NF4;
        int i = base + tid;
        for (; i + 768 < end; i += 1024) {
            float4 v0 = D4[i];
            float4 v1 = D4[i + 256];
            float4 v2 = D4[i + 512];
            float4 v3 = D4[i + 768];
            if (v0.x < tauR) { int p = atomicAdd(&cnt, 1); buf[p] = v0.x; }
            if (v0.y < tauR) { int p = atomicAdd(&cnt, 1); buf[p] = v0.y; }
            if (v0.z < tauR) { int p = atomicAdd(&cnt, 1); buf[p] = v0.z; }
            if (v0.w < tauR) { int p = atomicAdd(&cnt, 1); buf[p] = v0.w; }
            if (v1.x < tauR) { int p = atomicAdd(&cnt, 1); buf[p] = v1.x; }
            if (v1.y < tauR) { int p = atomicAdd(&cnt, 1); buf[p] = v1.y; }
            if (v1.z < tauR) { int p = atomicAdd(&cnt, 1); buf[p] = v1.z; }
            if (v1.w < tauR) { int p = atomicAdd(&cnt, 1); buf[p] = v1.w; }
            if (v2.x < tauR) { int p = atomicAdd(&cnt, 1); buf[p] = v2.x; }
            if (v2.y < tauR) { int p = atomicAdd(&cnt, 1); buf[p] = v2.y; }
            if (v2.z < tauR) { int p = atomicAdd(&cnt, 1); buf[p] = v2.z; }
            if (v2.w < tauR) { int p = atomicAdd(&cnt, 1); buf[p] = v2.w; }
            if (v3.x < tauR) { int p = atomicAdd(&cnt, 1); buf[p] = v3.x; }
            if (v3.y < tauR) { int p = atomicAdd(&cnt, 1); buf[p] = v3.y; }
            if (v3.z < tauR) { int p = atomicAdd(&cnt, 1); buf[p] = v3.z; }
            if (v3.w < tauR) { int p = atomicAdd(&cnt, 1); buf[p] = v3.w; }
        }
        for (; i < end; i += 256) {
            float4 v = D4[i];
            if (v.x < tauR) { int p = atomicAdd(&cnt, 1); buf[p] = v.x; }
            if (v.y < tauR) { int p = atomicAdd(&cnt, 1); buf[p] = v.y; }
            if (v.z < tauR) { int p = atomicAdd(&cnt, 1); buf[p] = v.z; }
            if (v.w < tauR) { int p = atomicAdd(&cnt, 1); buf[p] = v.w; }
        }
        __syncthreads();
        if ((first_chunk && cnt > 0) || cnt >= CAP - 4096) {
            merge();
        }
        tauR = tau;
        first_chunk = false;
        base = end;
    }
    if (cnt > 0) merge();

    // ---- LID ----
    if (tid == 0) {
        float rk2 = sel[KSEL - 1];
        float s = 0.f;
        #pragma unroll
        for (int i = 1; i < KSEL - 1; i++)
            s += 0.5f * logf(sel[i] / rk2);
        int l = row / BB;
        int b = row % BB;
        out[b * LL + l] = -(20.0f / s);
    }
}

// ============================================================
extern "C" void kernel_launch(void* const* d_in, const int* in_sizes, int n_in,
                              void* d_out, int out_size) {
    const float* feats = (const float*)d_in[0];
    const float* bank  = (const float*)d_in[1];
    // d_in[2] (k) is fixed at 20 for this problem.

    qmean_kernel<<<(LL * BB * CC) / 8, 256>>>(feats);
    q2_kernel<<<(LL * BB + 7) / 8, 256>>>();

    dim3 gg(2, (NPTS + Bn - 1) / Bn, LL);   // (2, 391, 4)
    gemm_mma_kernel<<<gg, 256>>>(bank);

    topk_lid_kernel<<<LL * BB, 256>>>((float*)d_out);
}